// round 8
// baseline (speedup 1.0000x reference)
#include <cuda_runtime.h>
#include <cstdint>

#define B_ 8
#define C_ 256
#define H_ 128
#define W_ 128
#define HW_ (H_*W_)
#define NPIX (B_*HW_)

#define CG 32            // conv channel groups
#define CPG (C_/CG)      // 8 channels per group
#define RT 16            // output rows per conv block
#define SROWS 18         // staged input rows per block (RT + 2 halo)
#define TASKS (SROWS*32) // float4 staging tasks per channel

#define CSPLIT 4
#define CPS (C_/CSPLIT)

__device__ float2 g_part[CG * NPIX];     // conv partials
__device__ float2 g_off[NPIX];           // merged offsets

__device__ __forceinline__ unsigned long long pack2(float v) {
    unsigned long long r;
    asm("mov.b64 %0, {%1, %1};" : "=l"(r) : "f"(v));
    return r;
}
__device__ __forceinline__ void ffma2(unsigned long long& d,
                                      unsigned long long a,
                                      unsigned long long b) {
    asm("fma.rn.f32x2 %0, %1, %2, %0;" : "+l"(d) : "l"(a), "l"(b));
}
__device__ __forceinline__ void unpack2(unsigned long long v, float& lo, float& hi) {
    asm("mov.b64 {%0, %1}, %2;" : "=f"(lo), "=f"(hi) : "l"(v));
}
__device__ __forceinline__ void cpa16(uint32_t dst, const void* src) {
    asm volatile("cp.async.cg.shared.global [%0], [%1], 16;" :: "r"(dst), "l"(src));
}

// ---------------------------------------------------------------------------
// Kernel 1: offset conv partials. cp.async 3-stage smem pipeline (block-wide
// 18-row band per channel), f32x2 packed FMA, shuffle column halos.
// Grid: B_*(H_/RT)*CG = 2048 blocks, 128 threads.
// ---------------------------------------------------------------------------
__global__ __launch_bounds__(128) void conv_kernel(const float* __restrict__ x,
                                                   const float* __restrict__ wc) {
    const int tid  = threadIdx.x;
    const int lane = tid & 31;
    const int wrp  = tid >> 5;
    int bx = blockIdx.x;
    const int g  = bx & 31; bx >>= 5;
    const int hb = bx & 7;  bx >>= 3;
    const int b  = bx;
    const int h0b  = hb * RT;
    const int c0   = g * CPG;
    const int col0 = lane * 4;

    __shared__ float  sbuf[3][SROWS * 128];
    __shared__ float2 swp[CPG * 9];

    if (tid < CPG * 9)
        swp[tid] = make_float2(wc[c0 * 9 + tid], wc[C_ * 9 + c0 * 9 + tid]);

    // pre-zero out-of-image staged rows (only at image edges)
    if (hb == 0)  for (int i = tid; i < 128; i += 128)
        { sbuf[0][i] = 0.f; sbuf[1][i] = 0.f; sbuf[2][i] = 0.f; }
    if (hb == 7)  for (int i = tid; i < 128; i += 128)
        { sbuf[0][17*128+i] = 0.f; sbuf[1][17*128+i] = 0.f; sbuf[2][17*128+i] = 0.f; }

    // per-thread staging task table (channel-invariant): 5 tasks max
    bool     tval[5];
    int      tg[5];        // gmem float offset within channel plane
    uint32_t ts[5];        // smem byte offset within one buffer
#pragma unroll
    for (int k = 0; k < 5; k++) {
        const int task = tid + k * 128;
        const int s  = task >> 5;
        const int cg4 = (task & 31) * 4;
        const int hr = h0b - 1 + s;
        tval[k] = (task < TASKS) && (hr >= 0) && (hr < H_);
        tg[k]   = hr * W_ + cg4;
        ts[k]   = (uint32_t)(s * 128 + cg4) * 4u;
    }

    const float* xb = x + (size_t)(b * C_ + c0) * HW_;
    const uint32_t sb0 = (uint32_t)__cvta_generic_to_shared(&sbuf[0][0]);

    // prologue: stage channel 0 into buffer 0
    {
        const float* xc = xb;
#pragma unroll
        for (int k = 0; k < 5; k++) if (tval[k]) cpa16(sb0 + ts[k], xc + tg[k]);
        asm volatile("cp.async.commit_group;");
    }
    __syncthreads();   // pre-zero + weights visible

    unsigned long long acc[4][4];
#pragma unroll
    for (int r = 0; r < 4; r++)
#pragma unroll
        for (int j = 0; j < 4; j++) acc[r][j] = 0ull;

    int wb = 1;  // next write buffer
    int cb = 0;  // consume buffer

#pragma unroll 1
    for (int c = 0; c < CPG; c++) {
        if (c + 1 < CPG) {
            const float* xc = xb + (size_t)(c + 1) * HW_;
            const uint32_t sbb = sb0 + (uint32_t)wb * (SROWS * 128 * 4);
#pragma unroll
            for (int k = 0; k < 5; k++) if (tval[k]) cpa16(sbb + ts[k], xc + tg[k]);
            asm volatile("cp.async.commit_group;");
            asm volatile("cp.async.wait_group 1;");
        } else {
            asm volatile("cp.async.wait_group 0;");
        }
        __syncthreads();

        const float* sbc = &sbuf[cb][0];
        float4 f[6];
#pragma unroll
        for (int r = 0; r < 6; r++)
            f[r] = *(const float4*)(sbc + (wrp * 4 + r) * 128 + col0);

        float colv[6][6];
#pragma unroll
        for (int r = 0; r < 6; r++) {
            float lh = __shfl_up_sync(0xffffffffu, f[r].w, 1);
            float rh = __shfl_down_sync(0xffffffffu, f[r].x, 1);
            if (lane == 0)  lh = 0.f;
            if (lane == 31) rh = 0.f;
            colv[r][0] = lh;   colv[r][1] = f[r].x; colv[r][2] = f[r].y;
            colv[r][3] = f[r].z; colv[r][4] = f[r].w; colv[r][5] = rh;
        }

        unsigned long long wp[9];
#pragma unroll
        for (int k = 0; k < 9; k++)
            wp[k] = *(const unsigned long long*)&swp[c * 9 + k];

#pragma unroll
        for (int ri = 0; ri < 6; ri++)
#pragma unroll
            for (int ci = 0; ci < 6; ci++) {
                const unsigned long long v2 = pack2(colv[ri][ci]);
#pragma unroll
                for (int kh = 0; kh < 3; kh++) {
                    const int rr = ri - kh;
                    if (rr < 0 || rr > 3) continue;
#pragma unroll
                    for (int kw = 0; kw < 3; kw++) {
                        const int j = ci - kw;
                        if (j < 0 || j > 3) continue;
                        ffma2(acc[rr][j], wp[kh * 3 + kw], v2);
                    }
                }
            }

        cb = (cb == 2) ? 0 : cb + 1;
        wb = (wb == 2) ? 0 : wb + 1;
    }

    float2* gp = g_part + (size_t)g * NPIX + b * HW_;
    const int h0 = h0b + wrp * 4;
#pragma unroll
    for (int rr = 0; rr < 4; rr++)
#pragma unroll
        for (int j = 0; j < 4; j++) {
            float axv, ayv;
            unpack2(acc[rr][j], axv, ayv);
            gp[(h0 + rr) * W_ + col0 + j] = make_float2(axv, ayv);
        }
}

// ---------------------------------------------------------------------------
// Kernel 1.5: merge the 32 partials.
// ---------------------------------------------------------------------------
__global__ __launch_bounds__(256) void reduce_kernel() {
    const int i = blockIdx.x * 256 + threadIdx.x;
    float ox = 0.f, oy = 0.f;
#pragma unroll
    for (int g = 0; g < CG; g++) {
        const float2 p = g_part[(size_t)g * NPIX + i];
        ox += p.x; oy += p.y;
    }
    g_off[i] = make_float2(ox, oy);
}

// ---------------------------------------------------------------------------
// Kernel 2: bilinear gather; aligned LDG.64 + predicated extra LDG.32,
// branchless selects. Grid: B_*H_*CSPLIT = 4096 blocks, 128 threads.
// ---------------------------------------------------------------------------
__global__ __launch_bounds__(128) void sample_kernel(const float* __restrict__ x,
                                                     const float* __restrict__ bc,
                                                     float* __restrict__ out) {
    const int w = threadIdx.x;
    int bx = blockIdx.x;
    const int s = bx & (CSPLIT - 1); bx >>= 2;
    const int h = bx & (H_ - 1);
    const int b = bx >> 7;
    const int pix = (b * H_ + h) * W_ + w;

    const float2 o = g_off[pix];
    float px = (float)h + o.x + bc[0];
    float py = (float)w + o.y + bc[1];
    px = fminf(fmaxf(px, 0.f), (float)(H_ - 2));
    py = fminf(fmaxf(py, 0.f), (float)(W_ - 2));

    const float fx = floorf(px), fy = floorf(py);
    const float dx = px - fx,    dy = py - fy;
    const float w00 = (1.f - dx) * (1.f - dy);
    const float w01 = (1.f - dx) * dy;
    const float w10 = dx * (1.f - dy);
    const float w11 = dx * dy;

    const int qx = (int)fx, qy = (int)fy;
    const int e  = qy & ~1;
    const unsigned odd = (unsigned)(qy & 1);

    const float* rb = x   + ((size_t)b * C_ + s * CPS) * HW_ + qx * W_ + e;
    float*       op = out + ((size_t)b * C_ + s * CPS) * HW_ + h * W_ + w;

#pragma unroll 8
    for (int c = 0; c < CPS; c++) {
        const float2 fa = __ldg((const float2*)rb);          // row qx:   e, e+1
        const float2 fb = __ldg((const float2*)(rb + W_));   // row qx+1: e, e+1
        float xt0 = 0.f, xt1 = 0.f;                          // e+2 values, odd only
        asm volatile("{\n\t"
                     ".reg .pred p;\n\t"
                     "setp.ne.u32 p, %2, 0;\n\t"
                     "@p ld.global.nc.f32 %0, [%3];\n\t"
                     "@p ld.global.nc.f32 %1, [%4];\n\t"
                     "}"
                     : "+f"(xt0), "+f"(xt1)
                     : "r"(odd), "l"(rb + 2), "l"(rb + W_ + 2));
        const float v00 = odd ? fa.y : fa.x;
        const float v01 = odd ? xt0  : fa.y;
        const float v10 = odd ? fb.y : fb.x;
        const float v11 = odd ? xt1  : fb.y;
        *op = fmaf(w00, v00, fmaf(w01, v01, fmaf(w10, v10, w11 * v11)));
        rb += HW_; op += HW_;
    }
}

// ---------------------------------------------------------------------------
extern "C" void kernel_launch(void* const* d_in, const int* in_sizes, int n_in,
                              void* d_out, int out_size) {
    const float* x  = (const float*)d_in[0];   // [8,256,128,128]
    const float* wc = (const float*)d_in[1];   // [2,256,3,3]
    const float* bc = (const float*)d_in[2];   // [2]
    float* out = (float*)d_out;                // [8,256,128,128,1]

    conv_kernel<<<B_ * (H_ / RT) * CG, 128>>>(x, wc);
    reduce_kernel<<<NPIX / 256, 256>>>();
    sample_kernel<<<B_ * H_ * CSPLIT, 128>>>(x, bc, out);
}

// round 9
// speedup vs baseline: 1.1230x; 1.1230x over previous
#include <cuda_runtime.h>

#define B_ 8
#define C_ 256
#define H_ 128
#define W_ 128
#define HW_ (H_*W_)
#define NPIX (B_*HW_)

#define CG 16            // conv channel groups
#define CPG (C_/CG)      // 16 channels per group
#define RT 16            // output rows per conv block

#define CSPLIT 4
#define CPS (C_/CSPLIT)

__device__ float2 g_part[CG * NPIX];     // conv partials (16.8 MB)
__device__ float2 g_off[NPIX];           // final clamped sample coords (px,py)

__device__ __forceinline__ unsigned long long pack2(float v) {
    unsigned long long r;
    asm("mov.b64 %0, {%1, %1};" : "=l"(r) : "f"(v));
    return r;
}
__device__ __forceinline__ void ffma2(unsigned long long& d,
                                      unsigned long long a,
                                      unsigned long long b) {
    asm("fma.rn.f32x2 %0, %1, %2, %0;" : "+l"(d) : "l"(a), "l"(b));
}
__device__ __forceinline__ void unpack2(unsigned long long v, float& lo, float& hi) {
    asm("mov.b64 {%0, %1}, %2;" : "=f"(lo), "=f"(hi) : "l"(v));
}
__device__ __forceinline__ void stcs(float* p, float v) {
    asm volatile("st.global.cs.f32 [%0], %1;" :: "l"(p), "f"(v));
}

// ---------------------------------------------------------------------------
// Kernel 1 (r3 form): offset conv partials, f32x2 packed, shuffle halos.
// Grid: B_*(H_/RT)*CG = 1024 blocks, 128 threads.
// ---------------------------------------------------------------------------
__global__ __launch_bounds__(128) void conv_kernel(const float* __restrict__ x,
                                                   const float* __restrict__ wc) {
    const int lane = threadIdx.x & 31;
    const int wrp  = threadIdx.x >> 5;
    int bx = blockIdx.x;
    const int g  = bx & 15; bx >>= 4;
    const int hb = bx & 7;  bx >>= 3;
    const int b  = bx;
    const int h0   = hb * RT + wrp * 4;
    const int c0   = g * CPG;
    const int col0 = lane * 4;

    __shared__ float2 swp[CPG * 9];
    for (int i = threadIdx.x; i < CPG * 9; i += 128)
        swp[i] = make_float2(wc[c0 * 9 + i], wc[C_ * 9 + c0 * 9 + i]);
    __syncthreads();

    unsigned long long acc[4][4];
#pragma unroll
    for (int r = 0; r < 4; r++)
#pragma unroll
        for (int j = 0; j < 4; j++) acc[r][j] = 0ull;

    const float* xb = x + (size_t)(b * C_ + c0) * HW_;

#pragma unroll 1
    for (int c = 0; c < CPG; c++) {
        const float* xc = xb + c * HW_;
        float4 f[6];
#pragma unroll
        for (int r = 0; r < 6; r++) {
            const int hr = h0 - 1 + r;
            if (hr >= 0 && hr < H_) f[r] = *(const float4*)(xc + hr * W_ + col0);
            else                    f[r] = make_float4(0.f, 0.f, 0.f, 0.f);
        }

        float colv[6][6];
#pragma unroll
        for (int r = 0; r < 6; r++) {
            float lh = __shfl_up_sync(0xffffffffu, f[r].w, 1);
            float rh = __shfl_down_sync(0xffffffffu, f[r].x, 1);
            if (lane == 0)  lh = 0.f;
            if (lane == 31) rh = 0.f;
            colv[r][0] = lh;   colv[r][1] = f[r].x; colv[r][2] = f[r].y;
            colv[r][3] = f[r].z; colv[r][4] = f[r].w; colv[r][5] = rh;
        }

        unsigned long long wp[9];
#pragma unroll
        for (int k = 0; k < 9; k++)
            wp[k] = *(const unsigned long long*)&swp[c * 9 + k];

#pragma unroll
        for (int ri = 0; ri < 6; ri++)
#pragma unroll
            for (int ci = 0; ci < 6; ci++) {
                const unsigned long long v2 = pack2(colv[ri][ci]);
#pragma unroll
                for (int kh = 0; kh < 3; kh++) {
                    const int rr = ri - kh;
                    if (rr < 0 || rr > 3) continue;
#pragma unroll
                    for (int kw = 0; kw < 3; kw++) {
                        const int j = ci - kw;
                        if (j < 0 || j > 3) continue;
                        ffma2(acc[rr][j], wp[kh * 3 + kw], v2);
                    }
                }
            }
    }

    float2* gp = g_part + (size_t)g * NPIX + b * HW_;
#pragma unroll
    for (int rr = 0; rr < 4; rr++)
#pragma unroll
        for (int j = 0; j < 4; j++) {
            float axv, ayv;
            unpack2(acc[rr][j], axv, ayv);
            gp[(h0 + rr) * W_ + col0 + j] = make_float2(axv, ayv);
        }
}

// ---------------------------------------------------------------------------
// Kernel 1.5: merge partials + bias + base grid + clamp -> final (px,py).
// Grid: NPIX/256 blocks, 256 threads (thread = one pixel).
// ---------------------------------------------------------------------------
__global__ __launch_bounds__(256) void reduce_kernel(const float* __restrict__ bc) {
    const int i = blockIdx.x * 256 + threadIdx.x;
    float ox = bc[0], oy = bc[1];
#pragma unroll
    for (int g = 0; g < CG; g++) {
        const float2 p = __ldg(&g_part[(size_t)g * NPIX + i]);
        ox += p.x; oy += p.y;
    }
    const int h = (i >> 7) & (H_ - 1);
    const int w = i & (W_ - 1);
    float px = (float)h + ox;
    float py = (float)w + oy;
    px = fminf(fmaxf(px, 0.f), (float)(H_ - 2));
    py = fminf(fmaxf(py, 0.f), (float)(W_ - 2));
    g_off[i] = make_float2(px, py);
}

// ---------------------------------------------------------------------------
// Kernel 2: bilinear gather (r2 form) + streaming stores.
// Grid: B_*H_*CSPLIT = 4096 blocks, 128 threads.
// ---------------------------------------------------------------------------
__global__ __launch_bounds__(128) void sample_kernel(const float* __restrict__ x,
                                                     float* __restrict__ out) {
    const int w = threadIdx.x;
    int bx = blockIdx.x;
    const int s = bx & (CSPLIT - 1); bx >>= 2;
    const int h = bx & (H_ - 1);
    const int b = bx >> 7;
    const int pix = (b * H_ + h) * W_ + w;

    const float2 p2 = __ldg(&g_off[pix]);
    const float px = p2.x, py = p2.y;

    const float fx = floorf(px), fy = floorf(py);
    const float dx = px - fx,    dy = py - fy;
    const float w00 = (1.f - dx) * (1.f - dy);
    const float w01 = (1.f - dx) * dy;
    const float w10 = dx * (1.f - dy);
    const float w11 = dx * dy;

    const int qx = (int)fx, qy = (int)fy;
    const float* xp = x   + ((size_t)b * C_ + s * CPS) * HW_ + qx * W_ + qy;
    float*       op = out + ((size_t)b * C_ + s * CPS) * HW_ + h * W_ + w;

#pragma unroll 8
    for (int c = 0; c < CPS; c++) {
        const float* p = xp + c * HW_;
        const float v00 = __ldg(p);
        const float v01 = __ldg(p + 1);
        const float v10 = __ldg(p + W_);
        const float v11 = __ldg(p + W_ + 1);
        stcs(op + c * HW_,
             fmaf(w00, v00, fmaf(w01, v01, fmaf(w10, v10, w11 * v11))));
    }
}

// ---------------------------------------------------------------------------
extern "C" void kernel_launch(void* const* d_in, const int* in_sizes, int n_in,
                              void* d_out, int out_size) {
    const float* x  = (const float*)d_in[0];   // [8,256,128,128]
    const float* wc = (const float*)d_in[1];   // [2,256,3,3]
    const float* bc = (const float*)d_in[2];   // [2]
    float* out = (float*)d_out;                // [8,256,128,128,1]

    conv_kernel<<<B_ * (H_ / RT) * CG, 128>>>(x, wc);
    reduce_kernel<<<NPIX / 256, 256>>>(bc);
    sample_kernel<<<B_ * H_ * CSPLIT, 128>>>(x, out);
}